// round 16
// baseline (speedup 1.0000x reference)
#include <cuda_runtime.h>
#include <cuda_fp16.h>
#include <cstdint>

#define C_OUT   256
#define C_IN    256
#define K_TOT   1280
#define KCH     64               // k per chunk -> 128B per row
#define NCH     (K_TOT / KCH)    // 20
#define MT      64               // rows per CTA
#define NTHREADS 512             // 16 warps: (wm 2) x (wn 4) x (kg 2)

// dynamic smem: A panel [20 sub][64 rows][128B] = 163840, B[2][256*128B] = 65536
#define SO_B    163840
#define SMEM_BYTES 229376        // 224 KB

__device__ __half g_Wh[C_OUT * K_TOT];   // W^T fp16 [n][k]

// ---------------- helpers ----------------
__device__ __forceinline__ uint32_t smem_u32(const void* p) {
    uint32_t a;
    asm("{ .reg .u64 t; cvta.to.shared.u64 t, %1; cvt.u32.u64 %0, t; }" : "=r"(a) : "l"(p));
    return a;
}
__device__ __forceinline__ uint32_t swz(uint32_t b) { return b ^ ((b >> 3) & 0x70); }

__device__ __forceinline__ void ldsm4(uint32_t* r, uint32_t a) {
    asm volatile("ldmatrix.sync.aligned.m8n8.x4.shared.b16 {%0,%1,%2,%3}, [%4];"
                 : "=r"(r[0]), "=r"(r[1]), "=r"(r[2]), "=r"(r[3]) : "r"(a));
}
__device__ __forceinline__ void mma16816(float* c, const uint32_t* a, const uint32_t* b) {
    asm volatile("mma.sync.aligned.m16n8k16.row.col.f32.f16.f16.f32 "
                 "{%0,%1,%2,%3}, {%4,%5,%6,%7}, {%8,%9}, {%0,%1,%2,%3};"
                 : "+f"(c[0]), "+f"(c[1]), "+f"(c[2]), "+f"(c[3])
                 : "r"(a[0]), "r"(a[1]), "r"(a[2]), "r"(a[3]), "r"(b[0]), "r"(b[1]));
}
__device__ __forceinline__ uint32_t pkh2(float a, float b) {
    __half2 h = __floats2half2_rn(a, b);
    return *reinterpret_cast<uint32_t*>(&h);
}
__device__ __forceinline__ void cp_async16(uint32_t saddr, const void* gptr) {
    asm volatile("cp.async.cg.shared.global [%0], [%1], 16;"
                 :: "r"(saddr), "l"(__cvta_generic_to_global(gptr)));
}

// ---------------- prep: W[k][n] fp32 -> Wt fp16 [n][k] ----------------
__global__ void prep_w_kernel(const float* __restrict__ W) {
    const int n = blockIdx.x;
    for (int k = threadIdx.x; k < K_TOT; k += blockDim.x)
        g_Wh[n * K_TOT + k] = __float2half_rn(W[(size_t)k * C_OUT + n]);
}

// ---------------- B staging: 256 rows x 64 fp16 = 2048 x 16B, 4 per thread ----------------
__device__ __forceinline__ void stage_B(uint32_t sb, int kc, int tid) {
    const uint32_t Bs = sb + SO_B + (kc & 1) * 32768;
    const int kg0 = kc * KCH;
    #pragma unroll
    for (int it = 0; it < 4; ++it) {
        const int s = tid + it * NTHREADS;
        const int n = s >> 3;
        const int k8 = (s & 7) * 8;
        cp_async16(Bs + swz(n * 128 + k8 * 2), g_Wh + n * K_TOT + kg0 + k8);
    }
}

// ---------------- main kernel ----------------
__global__ void __launch_bounds__(NTHREADS, 1)
smc_mma_kernel(const float* __restrict__ x,
               const int* __restrict__ idx1, const int* __restrict__ idx2,
               const int* __restrict__ idx3, const int* __restrict__ idx4,
               const float* __restrict__ bias, const float* __restrict__ gamma,
               const float* __restrict__ beta,
               float* __restrict__ out, int nRows)
{
    extern __shared__ char ds[];
    __shared__ float2 sPart[MT][4];

    const uint32_t sb = smem_u32(ds);
    const int tid  = threadIdx.x;
    const int lane = tid & 31;
    const int wid  = tid >> 5;
    const int kg   = wid >> 3;          // k-group 0/1
    const int wm   = (wid & 7) >> 2;    // row group (32 rows)
    const int wn   = wid & 3;           // col group (64 cols)
    const int bRow0 = blockIdx.x * MT;

    // ================= PROLOGUE: stage B0 + build full A panel =================
    stage_B(sb, 0, tid);

    {
        const int prow = tid >> 3;            // 0..63
        const int k8   = (tid & 7) * 8;       // 0..56
        int rgc = bRow0 + prow; if (rgc >= nRows) rgc = nRows - 1;
        const int ia = idx1[rgc], ib = idx2[rgc], ic = idx3[rgc], id_ = idx4[rgc];
        const uint32_t arow = swz((uint32_t)(prow * 128 + k8 * 2));

        // seg0 (subs 0..3): x converted
        #pragma unroll
        for (int q = 0; q < 4; ++q) {
            const float* xp = x + (size_t)rgc * C_IN + q * 64 + k8;
            const float4 v0 = *(const float4*)xp;
            const float4 v1 = *(const float4*)(xp + 4);
            *(uint4*)(ds + q * 8192 + arow) =
                make_uint4(pkh2(v0.x, v0.y), pkh2(v0.z, v0.w),
                           pkh2(v1.x, v1.y), pkh2(v1.z, v1.w));
        }
        // pair (a=x[idx1], c=x[idx3]): |a-c| -> subs 4..7, a+c -> subs 8..11
        #pragma unroll
        for (int q = 0; q < 4; ++q) {
            const float* ap = x + (size_t)ia * C_IN + q * 64 + k8;
            const float* cp = x + (size_t)ic * C_IN + q * 64 + k8;
            const float4 a0 = *(const float4*)ap;
            const float4 a1 = *(const float4*)(ap + 4);
            const float4 c0 = *(const float4*)cp;
            const float4 c1 = *(const float4*)(cp + 4);
            *(uint4*)(ds + (4 + q) * 8192 + arow) = make_uint4(
                pkh2(fabsf(a0.x-c0.x), fabsf(a0.y-c0.y)), pkh2(fabsf(a0.z-c0.z), fabsf(a0.w-c0.w)),
                pkh2(fabsf(a1.x-c1.x), fabsf(a1.y-c1.y)), pkh2(fabsf(a1.z-c1.z), fabsf(a1.w-c1.w)));
            *(uint4*)(ds + (8 + q) * 8192 + arow) = make_uint4(
                pkh2(a0.x+c0.x, a0.y+c0.y), pkh2(a0.z+c0.z, a0.w+c0.w),
                pkh2(a1.x+c1.x, a1.y+c1.y), pkh2(a1.z+c1.z, a1.w+c1.w));
        }
        // pair (b=x[idx2], d=x[idx4]): |b-d| -> subs 12..15, b+d -> subs 16..19
        #pragma unroll
        for (int q = 0; q < 4; ++q) {
            const float* bp = x + (size_t)ib * C_IN + q * 64 + k8;
            const float* dp = x + (size_t)id_ * C_IN + q * 64 + k8;
            const float4 b0 = *(const float4*)bp;
            const float4 b1 = *(const float4*)(bp + 4);
            const float4 d0 = *(const float4*)dp;
            const float4 d1 = *(const float4*)(dp + 4);
            *(uint4*)(ds + (12 + q) * 8192 + arow) = make_uint4(
                pkh2(fabsf(b0.x-d0.x), fabsf(b0.y-d0.y)), pkh2(fabsf(b0.z-d0.z), fabsf(b0.w-d0.w)),
                pkh2(fabsf(b1.x-d1.x), fabsf(b1.y-d1.y)), pkh2(fabsf(b1.z-d1.z), fabsf(b1.w-d1.w)));
            *(uint4*)(ds + (16 + q) * 8192 + arow) = make_uint4(
                pkh2(b0.x+d0.x, b0.y+d0.y), pkh2(b0.z+d0.z, b0.w+d0.w),
                pkh2(b1.x+d1.x, b1.y+d1.y), pkh2(b1.z+d1.z, b1.w+d1.w));
        }
    }
    asm volatile("cp.async.wait_all;" ::: "memory");
    __syncthreads();

    // ================= MAINLOOP: B-only staging =================
    float acc[2][8][4];
    #pragma unroll
    for (int i = 0; i < 2; i++)
        #pragma unroll
        for (int j = 0; j < 8; j++)
            #pragma unroll
            for (int e = 0; e < 4; e++) acc[i][j][e] = 0.f;

    const int lA_row = wm * 32 + (lane & 7) + ((lane >> 3) & 1) * 8;  // + mt*16
    const int lA_k8  = ((lane >> 4) & 1) * 8;
    const int lB_n   = wn * 64 + (lane & 7) + ((lane >> 4) & 1) * 8;  // + ng*16
    const int lB_k8  = ((lane >> 3) & 1) * 8;

    for (int kc = 0; kc < NCH; ++kc) {
        if (kc + 1 < NCH) stage_B(sb, kc + 1, tid);

        const uint32_t Ab = sb + kc * 8192;
        const uint32_t Bb = sb + SO_B + (kc & 1) * 32768;

        // this warp handles ks = kg and kg+2
        #pragma unroll
        for (int k2 = 0; k2 < 2; ++k2) {
            const int kb = (kg + k2 * 2) * 16;
            uint32_t a0[4], a1[4];
            ldsm4(a0, Ab + swz((uint32_t)(lA_row        * 128 + (kb + lA_k8) * 2)));
            ldsm4(a1, Ab + swz((uint32_t)((lA_row + 16) * 128 + (kb + lA_k8) * 2)));
            #pragma unroll
            for (int ng = 0; ng < 4; ++ng) {
                const uint32_t boff = swz((uint32_t)((lB_n + ng * 16) * 128 + (kb + lB_k8) * 2));
                uint32_t bh[4];
                ldsm4(bh, Bb + boff);
                mma16816(acc[0][2*ng+0], a0, bh + 0);
                mma16816(acc[0][2*ng+1], a0, bh + 2);
                mma16816(acc[1][2*ng+0], a1, bh + 0);
                mma16816(acc[1][2*ng+1], a1, bh + 2);
            }
        }
        asm volatile("cp.async.wait_all;" ::: "memory");
        __syncthreads();
    }

    // ================= EPILOGUE: merge kg pairs, then LN + GELU =================
    // exchange buffer over the (now dead) A panel, padded stride to dodge bank conflicts
    float* ex = (float*)ds;                  // [64][264] floats
    #define EXS 264

    if (kg == 1) {
        #pragma unroll
        for (int mt = 0; mt < 2; ++mt)
            #pragma unroll
            for (int nt = 0; nt < 8; ++nt) {
                const int r = wm * 32 + mt * 16 + (lane >> 2);
                const int c = wn * 64 + nt * 8 + (lane & 3) * 2;
                *(float2*)&ex[r * EXS + c]       = make_float2(acc[mt][nt][0], acc[mt][nt][1]);
                *(float2*)&ex[(r + 8) * EXS + c] = make_float2(acc[mt][nt][2], acc[mt][nt][3]);
            }
    }
    __syncthreads();

    if (kg == 0) {
        #pragma unroll
        for (int mt = 0; mt < 2; ++mt)
            #pragma unroll
            for (int nt = 0; nt < 8; ++nt) {
                const int r = wm * 32 + mt * 16 + (lane >> 2);
                const int c = wn * 64 + nt * 8 + (lane & 3) * 2;
                const float2 p0 = *(const float2*)&ex[r * EXS + c];
                const float2 p1 = *(const float2*)&ex[(r + 8) * EXS + c];
                acc[mt][nt][0] += p0.x; acc[mt][nt][1] += p0.y;
                acc[mt][nt][2] += p1.x; acc[mt][nt][3] += p1.y;
            }

        const int cbase = wn * 64 + (lane & 3) * 2;

        #pragma unroll
        for (int nt = 0; nt < 8; ++nt) {
            const float2 bv = *(const float2*)(bias + cbase + nt * 8);
            #pragma unroll
            for (int mt = 0; mt < 2; ++mt) {
                acc[mt][nt][0] += bv.x; acc[mt][nt][1] += bv.y;
                acc[mt][nt][2] += bv.x; acc[mt][nt][3] += bv.y;
            }
        }

        #pragma unroll
        for (int mt = 0; mt < 2; ++mt)
            #pragma unroll
            for (int h = 0; h < 2; ++h) {
                float s = 0.f, s2 = 0.f;
                #pragma unroll
                for (int nt = 0; nt < 8; ++nt) {
                    const float y0 = acc[mt][nt][h*2], y1 = acc[mt][nt][h*2+1];
                    s += y0 + y1; s2 += y0*y0 + y1*y1;
                }
                s  += __shfl_xor_sync(0xffffffffu, s, 1);
                s2 += __shfl_xor_sync(0xffffffffu, s2, 1);
                s  += __shfl_xor_sync(0xffffffffu, s, 2);
                s2 += __shfl_xor_sync(0xffffffffu, s2, 2);
                if ((lane & 3) == 0) {
                    const int row = wm * 32 + mt * 16 + h * 8 + (lane >> 2);
                    sPart[row][wn] = make_float2(s, s2);
                }
            }
    }
    __syncthreads();

    if (kg == 0) {
        const int cbase = wn * 64 + (lane & 3) * 2;
        float2 gv[8], ev[8];
        #pragma unroll
        for (int nt = 0; nt < 8; ++nt) {
            gv[nt] = *(const float2*)(gamma + cbase + nt * 8);
            ev[nt] = *(const float2*)(beta  + cbase + nt * 8);
        }

        #pragma unroll
        for (int mt = 0; mt < 2; ++mt)
            #pragma unroll
            for (int h = 0; h < 2; ++h) {
                const int row = wm * 32 + mt * 16 + h * 8 + (lane >> 2);
                const float2 p0 = sPart[row][0], p1 = sPart[row][1];
                const float2 p2 = sPart[row][2], p3 = sPart[row][3];
                const float S  = p0.x + p1.x + p2.x + p3.x;
                const float S2 = p0.y + p1.y + p2.y + p3.y;
                const float mu = S * (1.0f / 256.0f);
                const float var = S2 * (1.0f / 256.0f) - mu * mu;
                const float rstd = rsqrtf(var + 1e-5f);
                const int rg = bRow0 + row;
                if (rg < nRows) {
                    #pragma unroll
                    for (int nt = 0; nt < 8; ++nt) {
                        const float2 xv = *(const float2*)(x + (size_t)rg * C_IN + cbase + nt * 8);
                        const float t0 = (acc[mt][nt][h*2]   - mu) * rstd * gv[nt].x + ev[nt].x + xv.x;
                        const float t1 = (acc[mt][nt][h*2+1] - mu) * rstd * gv[nt].y + ev[nt].y + xv.y;
                        *(float2*)(out + (size_t)rg * C_IN + cbase + nt * 8) =
                            make_float2(t0 * normcdff(t0), t1 * normcdff(t1));
                    }
                }
            }
    }
}

extern "C" void kernel_launch(void* const* d_in, const int* in_sizes, int n_in,
                              void* d_out, int out_size)
{
    const float* x     = (const float*)d_in[0];
    const int*   idx1  = (const int*)d_in[1];
    const int*   idx2  = (const int*)d_in[2];
    const int*   idx3  = (const int*)d_in[3];
    const int*   idx4  = (const int*)d_in[4];
    const float* W     = (const float*)d_in[5];
    const float* bias  = (const float*)d_in[6];
    const float* gamma = (const float*)d_in[7];
    const float* beta  = (const float*)d_in[8];
    float* out = (float*)d_out;

    const int n = in_sizes[1];
    const int grid = (n + MT - 1) / MT;

    cudaFuncSetAttribute(smc_mma_kernel,
                         cudaFuncAttributeMaxDynamicSharedMemorySize, SMEM_BYTES);

    prep_w_kernel<<<C_OUT, 256>>>(W);
    smc_mma_kernel<<<grid, NTHREADS, SMEM_BYTES>>>(
        x, idx1, idx2, idx3, idx4, bias, gamma, beta, out, n);
}

// round 17
// speedup vs baseline: 1.1492x; 1.1492x over previous
#include <cuda_runtime.h>
#include <cuda_fp16.h>
#include <cstdint>

#define C_OUT   256
#define C_IN    256
#define K_TOT   1280
#define KCH     64               // k per chunk (fp16) -> 128B per row
#define NCH     (K_TOT / KCH)    // 20
#define MT      64               // rows per CTA
#define NTHREADS 256             // 8 warps: 2x4 warp grid, warp tile 32x64
#define PN_MAX  100352

// dynamic smem: A[2][64*128B] @0 (2x8KB), B[2][256*128B] @16384 (2x32KB)
#define SO_A    0
#define SO_B    16384
#define SMEM_BYTES 81920

__device__ __half g_Wh[C_OUT * K_TOT];                 // W^T fp16 [n][k]
__device__ __half g_patch[(size_t)PN_MAX * K_TOT];     // fp16 patch [N][1280]

// ---------------- helpers ----------------
__device__ __forceinline__ uint32_t smem_u32(const void* p) {
    uint32_t a;
    asm("{ .reg .u64 t; cvta.to.shared.u64 t, %1; cvt.u32.u64 %0, t; }" : "=r"(a) : "l"(p));
    return a;
}
__device__ __forceinline__ uint32_t swz(uint32_t b) { return b ^ ((b >> 3) & 0x70); }

__device__ __forceinline__ void ldsm4(uint32_t* r, uint32_t a) {
    asm volatile("ldmatrix.sync.aligned.m8n8.x4.shared.b16 {%0,%1,%2,%3}, [%4];"
                 : "=r"(r[0]), "=r"(r[1]), "=r"(r[2]), "=r"(r[3]) : "r"(a));
}
__device__ __forceinline__ void mma16816(float* c, const uint32_t* a, const uint32_t* b) {
    asm volatile("mma.sync.aligned.m16n8k16.row.col.f32.f16.f16.f32 "
                 "{%0,%1,%2,%3}, {%4,%5,%6,%7}, {%8,%9}, {%0,%1,%2,%3};"
                 : "+f"(c[0]), "+f"(c[1]), "+f"(c[2]), "+f"(c[3])
                 : "r"(a[0]), "r"(a[1]), "r"(a[2]), "r"(a[3]), "r"(b[0]), "r"(b[1]));
}
__device__ __forceinline__ uint32_t pkh2(float a, float b) {
    __half2 h = __floats2half2_rn(a, b);
    return *reinterpret_cast<uint32_t*>(&h);
}
__device__ __forceinline__ void cp_async16(uint32_t saddr, const void* gptr) {
    asm volatile("cp.async.cg.shared.global [%0], [%1], 16;"
                 :: "r"(saddr), "l"(__cvta_generic_to_global(gptr)));
}
__device__ __forceinline__ void bar_sync(int id, int cnt) {
    asm volatile("bar.sync %0, %1;" :: "r"(id), "r"(cnt) : "memory");
}

// ---------------- prep: W[k][n] fp32 -> Wt fp16 [n][k] ----------------
__global__ void prep_w_kernel(const float* __restrict__ W) {
    const int n = blockIdx.x;
    for (int k = threadIdx.x; k < K_TOT; k += blockDim.x)
        g_Wh[n * K_TOT + k] = __float2half_rn(W[(size_t)k * C_OUT + n]);
}

// ---------------- prep: build full fp16 patch [N][1280] ----------------
__global__ void __launch_bounds__(512)
prep_patch_kernel(const float* __restrict__ x,
                  const int* __restrict__ idx1, const int* __restrict__ idx2,
                  const int* __restrict__ idx3, const int* __restrict__ idx4,
                  int nRows)
{
    const int row = blockIdx.x * 16 + (threadIdx.x >> 5);
    if (row >= nRows) return;
    const int c8 = (threadIdx.x & 31) * 8;

    const int ia = idx1[row], ib = idx2[row], ic = idx3[row], id = idx4[row];

    const float4 x0 = *(const float4*)(x + (size_t)row * C_IN + c8);
    const float4 x1 = *(const float4*)(x + (size_t)row * C_IN + c8 + 4);
    const float4 a0 = *(const float4*)(x + (size_t)ia * C_IN + c8);
    const float4 a1 = *(const float4*)(x + (size_t)ia * C_IN + c8 + 4);
    const float4 b0 = *(const float4*)(x + (size_t)ib * C_IN + c8);
    const float4 b1 = *(const float4*)(x + (size_t)ib * C_IN + c8 + 4);
    const float4 c0 = *(const float4*)(x + (size_t)ic * C_IN + c8);
    const float4 c1 = *(const float4*)(x + (size_t)ic * C_IN + c8 + 4);
    const float4 d0 = *(const float4*)(x + (size_t)id * C_IN + c8);
    const float4 d1 = *(const float4*)(x + (size_t)id * C_IN + c8 + 4);

    __half* pr = g_patch + (size_t)row * K_TOT;

    *(uint4*)(pr + 0*256 + c8) = make_uint4(pkh2(x0.x, x0.y), pkh2(x0.z, x0.w),
                                            pkh2(x1.x, x1.y), pkh2(x1.z, x1.w));
    *(uint4*)(pr + 1*256 + c8) = make_uint4(
        pkh2(fabsf(a0.x-c0.x), fabsf(a0.y-c0.y)), pkh2(fabsf(a0.z-c0.z), fabsf(a0.w-c0.w)),
        pkh2(fabsf(a1.x-c1.x), fabsf(a1.y-c1.y)), pkh2(fabsf(a1.z-c1.z), fabsf(a1.w-c1.w)));
    *(uint4*)(pr + 2*256 + c8) = make_uint4(
        pkh2(a0.x+c0.x, a0.y+c0.y), pkh2(a0.z+c0.z, a0.w+c0.w),
        pkh2(a1.x+c1.x, a1.y+c1.y), pkh2(a1.z+c1.z, a1.w+c1.w));
    *(uint4*)(pr + 3*256 + c8) = make_uint4(
        pkh2(fabsf(b0.x-d0.x), fabsf(b0.y-d0.y)), pkh2(fabsf(b0.z-d0.z), fabsf(b0.w-d0.w)),
        pkh2(fabsf(b1.x-d1.x), fabsf(b1.y-d1.y)), pkh2(fabsf(b1.z-d1.z), fabsf(b1.w-d1.w)));
    *(uint4*)(pr + 4*256 + c8) = make_uint4(
        pkh2(b0.x+d0.x, b0.y+d0.y), pkh2(b0.z+d0.z, b0.w+d0.w),
        pkh2(b1.x+d1.x, b1.y+d1.y), pkh2(b1.z+d1.z, b1.w+d1.w));
}

// ---------------- main kernel ----------------
__global__ void __launch_bounds__(NTHREADS, 2)
smc_mma_kernel(const float* __restrict__ x,
               const float* __restrict__ bias, const float* __restrict__ gamma,
               const float* __restrict__ beta,
               float* __restrict__ out, int nRows)
{
    extern __shared__ char ds[];
    __shared__ float2 sPart[MT][4];

    const uint32_t sb = smem_u32(ds);
    const int tid  = threadIdx.x;
    const int lane = tid & 31;
    const int wid  = tid >> 5;
    const int wm   = wid & 1;     // warp row group (32 rows)
    const int wn   = wid >> 1;    // warp col group (64 cols)
    const int bRow0 = blockIdx.x * MT;

    // dependency groups: A-group = same wm (4 warps, ids 1..2),
    //                    B-group = same wn (2 warps, ids 3..6)
    const int aGid = 1 + wm;
    const int bGid = 3 + wn;
    const int ai = wn * 32 + lane;   // 0..127 within A group
    const int bi = wm * 32 + lane;   // 0..63  within B group

    float acc[2][8][4];
    #pragma unroll
    for (int i = 0; i < 2; i++)
        #pragma unroll
        for (int j = 0; j < 8; j++)
            #pragma unroll
            for (int e = 0; e < 4; e++) acc[i][j][e] = 0.f;

    const int lA_row = wm * 32 + (lane & 7) + ((lane >> 3) & 1) * 8; // + mt*16
    const int lA_k8  = ((lane >> 4) & 1) * 8;
    const int lB_n   = wn * 64 + (lane & 7) + ((lane >> 4) & 1) * 8; // + ng*16
    const int lB_k8  = ((lane >> 3) & 1) * 8;

    // per-warp region staging: B cols for wn group, A rows for wm group
    auto stage_own = [&](int kc) {
        const uint32_t As = sb + SO_A + (kc & 1) * 8192;
        const uint32_t Bs = sb + SO_B + (kc & 1) * 32768;
        const int kg0 = kc * KCH;
        // B region: 64 n-rows x 64 k = 512 x 16B over 64 threads -> 8 each
        #pragma unroll
        for (int it = 0; it < 8; ++it) {
            const int s = bi + it * 64;
            const int n = wn * 64 + (s >> 3);
            const int k8 = (s & 7) * 8;
            cp_async16(Bs + swz(n * 128 + k8 * 2), g_Wh + n * K_TOT + kg0 + k8);
        }
        // A region: 32 rows x 64 k = 256 x 16B over 128 threads -> 2 each
        #pragma unroll
        for (int it = 0; it < 2; ++it) {
            const int s = ai + it * 128;
            const int row = wm * 32 + (s >> 3);
            const int k8 = (s & 7) * 8;
            int rgc = bRow0 + row; if (rgc >= nRows) rgc = nRows - 1;
            cp_async16(As + swz(row * 128 + k8 * 2),
                       g_patch + (size_t)rgc * K_TOT + kg0 + k8);
        }
    };

    stage_own(0);
    asm volatile("cp.async.wait_all;" ::: "memory");
    __syncthreads();

    for (int kc = 0; kc < NCH; ++kc) {
        if (kc + 1 < NCH) stage_own(kc + 1);

        const uint32_t Ab = sb + SO_A + (kc & 1) * 8192;
        const uint32_t Bb = sb + SO_B + (kc & 1) * 32768;

        #pragma unroll
        for (int ks = 0; ks < 4; ++ks) {
            const int kb = ks * 16;
            uint32_t a0[4], a1[4];
            ldsm4(a0, Ab + swz((uint32_t)(lA_row        * 128 + (kb + lA_k8) * 2)));
            ldsm4(a1, Ab + swz((uint32_t)((lA_row + 16) * 128 + (kb + lA_k8) * 2)));
            #pragma unroll
            for (int ng = 0; ng < 4; ++ng) {
                const uint32_t boff = swz((uint32_t)((lB_n + ng * 16) * 128 + (kb + lB_k8) * 2));
                uint32_t bh[4];
                ldsm4(bh, Bb + boff);
                mma16816(acc[0][2*ng+0], a0, bh + 0);
                mma16816(acc[0][2*ng+1], a0, bh + 2);
                mma16816(acc[1][2*ng+0], a1, bh + 0);
                mma16816(acc[1][2*ng+1], a1, bh + 2);
            }
        }
        asm volatile("cp.async.wait_all;" ::: "memory");
        bar_sync(aGid, 128);     // A rows [wm*32, +32) producers+consumers
        bar_sync(bGid, 64);      // B cols [wn*64, +64) producers+consumers
    }

    __syncthreads();   // re-align CTA before epilogue smem reuse

    // ---------------- epilogue: bias + LN + residual + exact GELU ----------------
    const int cbase = wn * 64 + (lane & 3) * 2;

    #pragma unroll
    for (int nt = 0; nt < 8; ++nt) {
        const float2 bv = *(const float2*)(bias + cbase + nt * 8);
        #pragma unroll
        for (int mt = 0; mt < 2; ++mt) {
            acc[mt][nt][0] += bv.x; acc[mt][nt][1] += bv.y;
            acc[mt][nt][2] += bv.x; acc[mt][nt][3] += bv.y;
        }
    }

    #pragma unroll
    for (int mt = 0; mt < 2; ++mt)
        #pragma unroll
        for (int h = 0; h < 2; ++h) {
            float s = 0.f, s2 = 0.f;
            #pragma unroll
            for (int nt = 0; nt < 8; ++nt) {
                const float y0 = acc[mt][nt][h*2], y1 = acc[mt][nt][h*2+1];
                s += y0 + y1; s2 += y0*y0 + y1*y1;
            }
            s  += __shfl_xor_sync(0xffffffffu, s, 1);
            s2 += __shfl_xor_sync(0xffffffffu, s2, 1);
            s  += __shfl_xor_sync(0xffffffffu, s, 2);
            s2 += __shfl_xor_sync(0xffffffffu, s2, 2);
            if ((lane & 3) == 0) {
                const int row = wm * 32 + mt * 16 + h * 8 + (lane >> 2);
                sPart[row][wn] = make_float2(s, s2);
            }
        }
    __syncthreads();

    float2 gv[8], ev[8];
    #pragma unroll
    for (int nt = 0; nt < 8; ++nt) {
        gv[nt] = *(const float2*)(gamma + cbase + nt * 8);
        ev[nt] = *(const float2*)(beta  + cbase + nt * 8);
    }

    #pragma unroll
    for (int mt = 0; mt < 2; ++mt)
        #pragma unroll
        for (int h = 0; h < 2; ++h) {
            const int row = wm * 32 + mt * 16 + h * 8 + (lane >> 2);
            const float2 p0 = sPart[row][0], p1 = sPart[row][1];
            const float2 p2 = sPart[row][2], p3 = sPart[row][3];
            const float S  = p0.x + p1.x + p2.x + p3.x;
            const float S2 = p0.y + p1.y + p2.y + p3.y;
            const float mu = S * (1.0f / 256.0f);
            const float var = S2 * (1.0f / 256.0f) - mu * mu;
            const float rstd = rsqrtf(var + 1e-5f);
            const int rg = bRow0 + row;
            if (rg < nRows) {
                #pragma unroll
                for (int nt = 0; nt < 8; ++nt) {
                    const float2 xv = *(const float2*)(x + (size_t)rg * C_IN + cbase + nt * 8);
                    const float t0 = (acc[mt][nt][h*2]   - mu) * rstd * gv[nt].x + ev[nt].x + xv.x;
                    const float t1 = (acc[mt][nt][h*2+1] - mu) * rstd * gv[nt].y + ev[nt].y + xv.y;
                    *(float2*)(out + (size_t)rg * C_IN + cbase + nt * 8) =
                        make_float2(t0 * normcdff(t0), t1 * normcdff(t1));
                }
            }
        }
}

extern "C" void kernel_launch(void* const* d_in, const int* in_sizes, int n_in,
                              void* d_out, int out_size)
{
    const float* x     = (const float*)d_in[0];
    const int*   idx1  = (const int*)d_in[1];
    const int*   idx2  = (const int*)d_in[2];
    const int*   idx3  = (const int*)d_in[3];
    const int*   idx4  = (const int*)d_in[4];
    const float* W     = (const float*)d_in[5];
    const float* bias  = (const float*)d_in[6];
    const float* gamma = (const float*)d_in[7];
    const float* beta  = (const float*)d_in[8];
    float* out = (float*)d_out;

    const int n = in_sizes[1];
    const int grid = (n + MT - 1) / MT;

    cudaFuncSetAttribute(smc_mma_kernel,
                         cudaFuncAttributeMaxDynamicSharedMemorySize, SMEM_BYTES);

    prep_w_kernel<<<C_OUT, 256>>>(W);
    prep_patch_kernel<<<(n + 15) / 16, 512>>>(x, idx1, idx2, idx3, idx4, n);
    smc_mma_kernel<<<grid, NTHREADS, SMEM_BYTES>>>(x, bias, gamma, beta, out, n);
}